// round 1
// baseline (speedup 1.0000x reference)
#include <cuda_runtime.h>

#define B   256
#define N   8192
#define C   32768
#define NSE 524288

// Scratch (device globals — no allocation allowed)
__device__ float g_w[NSE];          // exp(log_w)
__device__ float g_pT[(size_t)C * B]; // exp(child_ll) transposed [C][B], 33.5 MB
__device__ int   g_row_start[N + 1];

// K1: per-edge exp(log_w) + row boundary detection (rows are sorted, every row present)
__global__ void prep_edges(const float* __restrict__ logw, const int* __restrict__ rows) {
    int e = blockIdx.x * blockDim.x + threadIdx.x;
    if (e < NSE) {
        g_w[e] = __expf(logw[e]);
        int r = rows[e];
        if (e == 0 || rows[e - 1] != r) g_row_start[r] = e;
        if (e == 0) g_row_start[N] = NSE;
    }
}

// K2: tiled transpose + exp: pT[c][b] = exp(child_ll[b][c])
__global__ void transpose_exp(const float* __restrict__ ll) {
    __shared__ float tile[32][33];
    int c0 = blockIdx.x * 32, b0 = blockIdx.y * 32;
    int tx = threadIdx.x, ty = threadIdx.y;  // blockDim = (32, 8)
#pragma unroll
    for (int i = 0; i < 32; i += 8)
        tile[ty + i][tx] = ll[(size_t)(b0 + ty + i) * C + c0 + tx];
    __syncthreads();
#pragma unroll
    for (int i = 0; i < 32; i += 8)
        g_pT[(size_t)(c0 + ty + i) * B + b0 + tx] = __expf(tile[tx][ty + i]);
}

// K3: main gather-accumulate. 8 nodes per block; 64-lane group per node,
// each lane owns 4 consecutive batches (float4 from pT). z computed inline.
__global__ __launch_bounds__(512) void sum_kernel(const int* __restrict__ cols,
                                                  float* __restrict__ out) {
    __shared__ float s_res[8][B];
    int g    = threadIdx.x >> 6;
    int lane = threadIdx.x & 63;
    int node = blockIdx.x * 8 + g;

    int e0 = g_row_start[node];
    int e1 = g_row_start[node + 1];

    float ax = 0.f, ay = 0.f, az = 0.f, aw = 0.f, wsum = 0.f;
    const float4* pT4 = (const float4*)g_pT;

#pragma unroll 4
    for (int e = e0; e < e1; e++) {
        float we = __ldg(&g_w[e]);
        int   c  = __ldg(&cols[e]);
        float4 p = pT4[(size_t)c * (B / 4) + lane];
        ax = fmaf(we, p.x, ax);
        ay = fmaf(we, p.y, ay);
        az = fmaf(we, p.z, az);
        aw = fmaf(we, p.w, aw);
        wsum += we;
    }

    float lz = __logf(wsum);
    int b = lane * 4;
    s_res[g][b + 0] = __logf(ax) - lz;
    s_res[g][b + 1] = __logf(ay) - lz;
    s_res[g][b + 2] = __logf(az) - lz;
    s_res[g][b + 3] = __logf(aw) - lz;
    __syncthreads();

    // Transposed write-out: thread b writes 8 consecutive nodes = one 32B sector
    if (threadIdx.x < B) {
        int bb = threadIdx.x;
        float4 v0 = make_float4(s_res[0][bb], s_res[1][bb], s_res[2][bb], s_res[3][bb]);
        float4 v1 = make_float4(s_res[4][bb], s_res[5][bb], s_res[6][bb], s_res[7][bb]);
        float4* o = (float4*)(out + (size_t)bb * N + (size_t)blockIdx.x * 8);
        o[0] = v0;
        o[1] = v1;
    }
}

extern "C" void kernel_launch(void* const* d_in, const int* in_sizes, int n_in,
                              void* d_out, int out_size) {
    const float* child_ll = (const float*)d_in[0];  // [B, C]
    const float* log_w    = (const float*)d_in[1];  // [NSE]
    const int*   rows     = (const int*)d_in[2];    // [NSE], sorted
    const int*   cols     = (const int*)d_in[3];    // [NSE]
    float*       out      = (float*)d_out;          // [B, N]

    prep_edges<<<(NSE + 255) / 256, 256>>>(log_w, rows);
    dim3 tb(32, 8);
    dim3 tg(C / 32, B / 32);
    transpose_exp<<<tg, tb>>>(child_ll);
    sum_kernel<<<N / 8, 512>>>(cols, out);
}

// round 3
// speedup vs baseline: 1.3142x; 1.3142x over previous
#include <cuda_runtime.h>
#include <cuda_fp16.h>

#define B   256
#define N   8192
#define C   32768
#define NSE 524288

#define TRANS_BLOCKS ((C / 32) * (B / 32))   // 1024 * 8 = 8192
#define PREP_BLOCKS  (NSE / 4 / 256)         // 512

// Scratch (device globals — no allocation allowed)
__device__ float4 g_pT4[(size_t)C * B / 8];  // exp(child_ll) transposed [C][B] as fp16, 16.7 MB
__device__ float2 g_edge[NSE];               // {exp(log_w), col (bit-cast int)}
__device__ int    g_row_start[N + 1];

// K1 (fused): transpose+exp+fp16-pack for pT, AND edge prep, partitioned by blockIdx.
__global__ __launch_bounds__(256) void prep_kernel(const float* __restrict__ ll,
                                                   const float* __restrict__ logw,
                                                   const int*   __restrict__ rows,
                                                   const int*   __restrict__ cols) {
    int t = threadIdx.x;
    if (blockIdx.x < TRANS_BLOCKS) {
        // ---- transpose 32(b) x 32(c) tile, exp, pack to half ----
        __shared__ float tile[32][33];
        int tx = t & 31, ty = t >> 5;                 // ty 0..7
        int c0 = (blockIdx.x & (C / 32 - 1)) * 32;
        int b0 = (blockIdx.x >> 10) * 32;
#pragma unroll
        for (int i = 0; i < 32; i += 8)
            tile[ty + i][tx] = ll[(size_t)(b0 + ty + i) * C + c0 + tx];
        __syncthreads();
        int c_idx = t >> 3;          // 0..31
        int b_idx = (t & 7) * 4;     // 0,4,...,28
        __half2 h01 = __halves2half2(__float2half_rn(__expf(tile[b_idx + 0][c_idx])),
                                     __float2half_rn(__expf(tile[b_idx + 1][c_idx])));
        __half2 h23 = __halves2half2(__float2half_rn(__expf(tile[b_idx + 2][c_idx])),
                                     __float2half_rn(__expf(tile[b_idx + 3][c_idx])));
        __half* pT = (__half*)g_pT4;
        float2 pack;
        pack.x = __uint_as_float(*(const unsigned*)&h01);
        pack.y = __uint_as_float(*(const unsigned*)&h23);
        *(float2*)&pT[(size_t)(c0 + c_idx) * B + b0 + b_idx] = pack;
    } else {
        // ---- edge prep: 4 edges per thread, vectorized ----
        int e4 = (blockIdx.x - TRANS_BLOCKS) * 256 + t;   // group-of-4 index
        int e  = e4 * 4;
        float4 lw = __ldg(&((const float4*)logw)[e4]);
        int4   cc = __ldg(&((const int4*)cols)[e4]);
        int4   rr = __ldg(&((const int4*)rows)[e4]);
        g_edge[e + 0] = make_float2(__expf(lw.x), __int_as_float(cc.x));
        g_edge[e + 1] = make_float2(__expf(lw.y), __int_as_float(cc.y));
        g_edge[e + 2] = make_float2(__expf(lw.z), __int_as_float(cc.z));
        g_edge[e + 3] = make_float2(__expf(lw.w), __int_as_float(cc.w));
        // row boundaries (rows sorted, every row present)
        int rprev = (e == 0) ? -1 : __ldg(&rows[e - 1]);
        if (rr.x != rprev) g_row_start[rr.x] = e + 0;
        if (rr.y != rr.x)  g_row_start[rr.y] = e + 1;
        if (rr.z != rr.y)  g_row_start[rr.z] = e + 2;
        if (rr.w != rr.z)  g_row_start[rr.w] = e + 3;
        if (e == 0)        g_row_start[N]    = NSE;
    }
}

// K2: main gather-accumulate. 1 warp per node, 8 batches per lane (LDG.128 of 8 halves).
__global__ __launch_bounds__(256) void sum_kernel(float* __restrict__ out) {
    __shared__ float s_res[8][B];
    int warp = threadIdx.x >> 5;
    int lane = threadIdx.x & 31;
    int node = blockIdx.x * 8 + warp;

    int e0 = g_row_start[node];
    int e1 = g_row_start[node + 1];

    float a0 = 0.f, a1 = 0.f, a2 = 0.f, a3 = 0.f;
    float a4 = 0.f, a5 = 0.f, a6 = 0.f, a7 = 0.f, wsum = 0.f;

#pragma unroll 4
    for (int e = e0; e < e1; e++) {
        float2 ed = __ldg(&g_edge[e]);
        float  we = ed.x;
        int    c  = __float_as_int(ed.y);
        float4 raw = __ldg(&g_pT4[(size_t)c * 32 + lane]);
        const __half2* h = (const __half2*)&raw;
        float2 f;
        f = __half22float2(h[0]); a0 = fmaf(we, f.x, a0); a1 = fmaf(we, f.y, a1);
        f = __half22float2(h[1]); a2 = fmaf(we, f.x, a2); a3 = fmaf(we, f.y, a3);
        f = __half22float2(h[2]); a4 = fmaf(we, f.x, a4); a5 = fmaf(we, f.y, a5);
        f = __half22float2(h[3]); a6 = fmaf(we, f.x, a6); a7 = fmaf(we, f.y, a7);
        wsum += we;
    }

    float lz = __logf(wsum);
    float4 r0 = make_float4(__logf(a0) - lz, __logf(a1) - lz,
                            __logf(a2) - lz, __logf(a3) - lz);
    float4 r1 = make_float4(__logf(a4) - lz, __logf(a5) - lz,
                            __logf(a6) - lz, __logf(a7) - lz);
    float4* sr = (float4*)&s_res[warp][lane * 8];
    sr[0] = r0;
    sr[1] = r1;
    __syncthreads();

    // Transposed write-out: thread b writes 8 consecutive nodes = one 32B sector
    int bb = threadIdx.x;   // 0..255 == B
    float4 v0 = make_float4(s_res[0][bb], s_res[1][bb], s_res[2][bb], s_res[3][bb]);
    float4 v1 = make_float4(s_res[4][bb], s_res[5][bb], s_res[6][bb], s_res[7][bb]);
    float4* o = (float4*)(out + (size_t)bb * N + (size_t)blockIdx.x * 8);
    o[0] = v0;
    o[1] = v1;
}

extern "C" void kernel_launch(void* const* d_in, const int* in_sizes, int n_in,
                              void* d_out, int out_size) {
    const float* child_ll = (const float*)d_in[0];  // [B, C]
    const float* log_w    = (const float*)d_in[1];  // [NSE]
    const int*   rows     = (const int*)d_in[2];    // [NSE], sorted
    const int*   cols     = (const int*)d_in[3];    // [NSE]
    float*       out      = (float*)d_out;          // [B, N]

    prep_kernel<<<TRANS_BLOCKS + PREP_BLOCKS, 256>>>(child_ll, log_w, rows, cols);
    sum_kernel<<<N / 8, 256>>>(out);
}

// round 4
// speedup vs baseline: 1.4135x; 1.0755x over previous
#include <cuda_runtime.h>
#include <cuda_fp16.h>

#define B   256
#define N   8192
#define C   32768
#define NSE 524288

#define TRANS_BLOCKS ((C / 128) * (B / 32))  // 256 * 8 = 2048
#define PREP_BLOCKS  (NSE / 4 / 256)         // 512

// Scratch (device globals — no allocation allowed)
__device__ float4 g_pT4[(size_t)C * B / 8];  // exp(child_ll) transposed [C][B] as fp16, 16.7 MB
__device__ float2 g_edge[NSE];               // {exp(log_w), col (bit-cast int)}
__device__ int    g_row_start[N + 1];

// K1 (fused): transpose+exp+fp16-pack for pT (128c x 32b tiles), AND edge prep.
__global__ __launch_bounds__(256) void prep_kernel(const float* __restrict__ ll,
                                                   const float* __restrict__ logw,
                                                   const int*   __restrict__ rows,
                                                   const int*   __restrict__ cols) {
    int t = threadIdx.x;
    if (blockIdx.x < TRANS_BLOCKS) {
        __shared__ float tile[32][129];           // pad 129 -> conflict-free transposed read
        int c0 = (blockIdx.x & (C / 128 - 1)) * 128;
        int b0 = (blockIdx.x >> 8) * 32;
        int row = t >> 3;                          // 0..31 (batch)
        int v   = t & 7;                           // 0..7
        const float4* src = (const float4*)(ll + (size_t)(b0 + row) * C + c0);
#pragma unroll
        for (int j = 0; j < 4; j++) {              // 4 independent float4 loads (MLP=4)
            float4 x = __ldg(&src[v + j * 8]);
            int col = (v + j * 8) * 4;
            tile[row][col + 0] = x.x;
            tile[row][col + 1] = x.y;
            tile[row][col + 2] = x.z;
            tile[row][col + 3] = x.w;
        }
        __syncthreads();
        int c_loc = t >> 1;                        // 0..127 (child within tile)
        int bofs  = (t & 1) * 16;                  // 0 or 16
        uint4 outv[2];
        __half* hh = (__half*)outv;
#pragma unroll
        for (int j = 0; j < 16; j++)
            hh[j] = __float2half_rn(__expf(tile[bofs + j][c_loc]));
        __half* pT = (__half*)g_pT4;
        uint4* dst = (uint4*)&pT[(size_t)(c0 + c_loc) * B + b0 + bofs];
        dst[0] = outv[0];
        dst[1] = outv[1];
    } else {
        // ---- edge prep: 4 edges per thread, vectorized ----
        int e4 = (blockIdx.x - TRANS_BLOCKS) * 256 + t;
        int e  = e4 * 4;
        float4 lw = __ldg(&((const float4*)logw)[e4]);
        int4   cc = __ldg(&((const int4*)cols)[e4]);
        int4   rr = __ldg(&((const int4*)rows)[e4]);
        g_edge[e + 0] = make_float2(__expf(lw.x), __int_as_float(cc.x));
        g_edge[e + 1] = make_float2(__expf(lw.y), __int_as_float(cc.y));
        g_edge[e + 2] = make_float2(__expf(lw.z), __int_as_float(cc.z));
        g_edge[e + 3] = make_float2(__expf(lw.w), __int_as_float(cc.w));
        int rprev = (e == 0) ? -1 : __ldg(&rows[e - 1]);
        if (rr.x != rprev) g_row_start[rr.x] = e + 0;
        if (rr.y != rr.x)  g_row_start[rr.y] = e + 1;
        if (rr.z != rr.y)  g_row_start[rr.z] = e + 2;
        if (rr.w != rr.z)  g_row_start[rr.w] = e + 3;
        if (e == 0)        g_row_start[N]    = NSE;
    }
}

#define ACC(d, p) {                                                      \
    float we = d.x; wsum += we;                                          \
    const __half2* h = (const __half2*)&p;                               \
    float2 f;                                                            \
    f = __half22float2(h[0]); a0 = fmaf(we, f.x, a0); a1 = fmaf(we, f.y, a1); \
    f = __half22float2(h[1]); a2 = fmaf(we, f.x, a2); a3 = fmaf(we, f.y, a3); \
    f = __half22float2(h[2]); a4 = fmaf(we, f.x, a4); a5 = fmaf(we, f.y, a5); \
    f = __half22float2(h[3]); a6 = fmaf(we, f.x, a6); a7 = fmaf(we, f.y, a7); }

#define PTLOAD(d) __ldg((const float4*)(pTb + (unsigned)__float_as_uint(d.y) * 512u))

// K2: main gather-accumulate. 1 warp/node, 8 batches/lane, chunk-4 pipelined loads.
__global__ __launch_bounds__(256) void sum_kernel(float* __restrict__ out) {
    __shared__ float s_res[8][B];
    int warp = threadIdx.x >> 5;
    int lane = threadIdx.x & 31;
    int node = blockIdx.x * 8 + warp;

    int e0 = g_row_start[node];
    int e1 = g_row_start[node + 1];

    const char* pTb = (const char*)g_pT4 + lane * 16;

    float a0 = 0.f, a1 = 0.f, a2 = 0.f, a3 = 0.f;
    float a4 = 0.f, a5 = 0.f, a6 = 0.f, a7 = 0.f, wsum = 0.f;

    int e = e0;
    for (; e + 4 <= e1; e += 4) {
        // 4 independent edge loads, then 4 independent gathers: MLP=8
        float2 d0 = __ldcs(&g_edge[e + 0]);
        float2 d1 = __ldcs(&g_edge[e + 1]);
        float2 d2 = __ldcs(&g_edge[e + 2]);
        float2 d3 = __ldcs(&g_edge[e + 3]);
        float4 p0 = PTLOAD(d0);
        float4 p1 = PTLOAD(d1);
        float4 p2 = PTLOAD(d2);
        float4 p3 = PTLOAD(d3);
        ACC(d0, p0) ACC(d1, p1) ACC(d2, p2) ACC(d3, p3)
    }
    for (; e < e1; e++) {
        float2 d0 = __ldcs(&g_edge[e]);
        float4 p0 = PTLOAD(d0);
        ACC(d0, p0)
    }

    float lz = __logf(wsum);
    float4 r0 = make_float4(__logf(a0) - lz, __logf(a1) - lz,
                            __logf(a2) - lz, __logf(a3) - lz);
    float4 r1 = make_float4(__logf(a4) - lz, __logf(a5) - lz,
                            __logf(a6) - lz, __logf(a7) - lz);
    float4* sr = (float4*)&s_res[warp][lane * 8];
    sr[0] = r0;
    sr[1] = r1;
    __syncthreads();

    // Transposed write-out: thread b writes 8 consecutive nodes (one 32B sector)
    int bb = threadIdx.x;   // 0..255 == B
    float4 v0 = make_float4(s_res[0][bb], s_res[1][bb], s_res[2][bb], s_res[3][bb]);
    float4 v1 = make_float4(s_res[4][bb], s_res[5][bb], s_res[6][bb], s_res[7][bb]);
    float4* o = (float4*)(out + (size_t)bb * N + (size_t)blockIdx.x * 8);
    o[0] = v0;
    o[1] = v1;
}

extern "C" void kernel_launch(void* const* d_in, const int* in_sizes, int n_in,
                              void* d_out, int out_size) {
    const float* child_ll = (const float*)d_in[0];  // [B, C]
    const float* log_w    = (const float*)d_in[1];  // [NSE]
    const int*   rows     = (const int*)d_in[2];    // [NSE], sorted
    const int*   cols     = (const int*)d_in[3];    // [NSE]
    float*       out      = (float*)d_out;          // [B, N]

    prep_kernel<<<TRANS_BLOCKS + PREP_BLOCKS, 256>>>(child_ll, log_w, rows, cols);
    sum_kernel<<<N / 8, 256>>>(out);
}